// round 5
// baseline (speedup 1.0000x reference)
#include <cuda_runtime.h>
#include <cstdint>

#define N_NODES 100000
#define N_EDGES 1600000
#define D_IN    128
#define D_OUT   64
#define NBCH    ((N_NODES + 1023) / 1024)   // 98 scan chunks of 1024

// ---------------- device scratch (no runtime allocation allowed) -------------
__device__ float g_xw[(size_t)N_NODES * D_OUT];   // x @ W   (25.6 MB)
__device__ int   g_counts[N_NODES];
__device__ int   g_rowstart[N_NODES + 1];
__device__ int   g_cursor[N_NODES];
__device__ int   g_part[NBCH];
__device__ int   g_part_scan[NBCH];
__device__ int   g_is32;                          // 1 if edge indices are int32
__device__ int2  g_sedge[N_EDGES];                // (dst, weight-bits), sorted by src

// packed fp32x2 helpers (Blackwell f32x2 pipe, 2x fp32 FMA throughput;
// ptxas never auto-fuses to FFMA2 from C++ — must come in via PTX)
#define PACKDUP(out, f)                                                     \
    asm("mov.b64 %0, {%1, %2};" : "=l"(out)                                 \
        : "r"(__float_as_uint(f)), "r"(__float_as_uint(f)))
#define FMA2(d, a, b)                                                       \
    asm("fma.rn.f32x2 %0, %1, %2, %3;" : "=l"(d) : "l"(a), "l"(b), "l"(d))

__device__ __forceinline__ int load_idx(const void* p, int e, bool is32) {
    return is32 ? ((const int*)p)[e] : (int)((const long long*)p)[e];
}

// ---------------- dtype probe: int64 vs silently-demoted int32 ---------------
// int64 indices < N_NODES read as u64 are small; int32 index pairs read as
// u64 are huge whenever the high word (the next index) is nonzero.
// 64 samples (128 int32 words) -> P(miss | int32) ~ (1e-5)^64.
__global__ void k_detect(const unsigned long long* __restrict__ src) {
    __shared__ int bad;
    if (threadIdx.x == 0) bad = 0;
    __syncthreads();
    unsigned long long v = src[threadIdx.x];   // 512B valid in either dtype
    if (v >= (unsigned long long)N_NODES) atomicOr(&bad, 1);
    __syncthreads();
    if (threadIdx.x == 0) g_is32 = bad;
}

// ---------------- CSR build: zero -> histogram -> scan -> scatter ------------
__global__ void k_zero() {
    int i = blockIdx.x * blockDim.x + threadIdx.x;
    if (i < N_NODES) g_counts[i] = 0;
}

__global__ void k_hist(const void* __restrict__ esrc) {
    bool is32 = (g_is32 != 0);
    int t = blockIdx.x * blockDim.x + threadIdx.x;
#pragma unroll
    for (int j = 0; j < 2; j++) {
        int e = t + j * (N_EDGES / 2);          // two strided halves per thread
        if (e < N_EDGES) {
            int s = load_idx(esrc, e, is32);
            atomicAdd(&g_counts[s], 1);
        }
    }
}

__global__ void k_scan_a() {   // per-chunk (1024) sums
    __shared__ int sh[256];
    int tid  = threadIdx.x;
    int base = blockIdx.x * 1024 + tid * 4;
    int s = 0;
#pragma unroll
    for (int j = 0; j < 4; j++) {
        int i = base + j;
        if (i < N_NODES) s += g_counts[i];
    }
    sh[tid] = s;
    __syncthreads();
    for (int off = 128; off > 0; off >>= 1) {
        if (tid < off) sh[tid] += sh[tid + off];
        __syncthreads();
    }
    if (tid == 0) g_part[blockIdx.x] = sh[0];
}

__global__ void k_scan_b() {   // scan 98 partials (trivial, 1 thread)
    int run = 0;
    for (int b = 0; b < NBCH; b++) {
        g_part_scan[b] = run;
        run += g_part[b];
    }
    g_rowstart[N_NODES] = run;
}

__global__ void k_scan_c() {   // chunk-local exclusive scan + global offset
    __shared__ int sh[256];
    int tid  = threadIdx.x;
    int base = blockIdx.x * 1024 + tid * 4;
    int v[4];
    int s = 0;
#pragma unroll
    for (int j = 0; j < 4; j++) {
        int i = base + j;
        v[j] = (i < N_NODES) ? g_counts[i] : 0;
        s += v[j];
    }
    sh[tid] = s;
    __syncthreads();
    for (int off = 1; off < 256; off <<= 1) {   // inclusive Hillis-Steele
        int t = (tid >= off) ? sh[tid - off] : 0;
        __syncthreads();
        sh[tid] += t;
        __syncthreads();
    }
    int run = (tid ? sh[tid - 1] : 0) + g_part_scan[blockIdx.x];
#pragma unroll
    for (int j = 0; j < 4; j++) {
        int i = base + j;
        if (i < N_NODES) {
            g_rowstart[i] = run;
            g_cursor[i]   = run;
        }
        run += v[j];
    }
}

__global__ void k_scatter(const void* __restrict__ esrc,
                          const void* __restrict__ edst,
                          const float* __restrict__ ew) {
    bool is32 = (g_is32 != 0);
    int t = blockIdx.x * blockDim.x + threadIdx.x;
#pragma unroll
    for (int j = 0; j < 2; j++) {
        int e = t + j * (N_EDGES / 2);
        if (e < N_EDGES) {
            int s   = load_idx(esrc, e, is32);
            int pos = atomicAdd(&g_cursor[s], 1);
            g_sedge[pos] = make_int2(load_idx(edst, e, is32),
                                     __float_as_int(ew[e]));
        }
    }
}

// ---------------- dense GEMM: g_xw = x @ W  (128x64 tile per block) ----------
// 128 threads, each computes 8 rows x 8 cols with f32x2 accumulators.
__global__ __launch_bounds__(128) void k_gemm(const float* __restrict__ x,
                                              const float* __restrict__ w) {
    __shared__ float xs[32][128];   // [k][row], 16 KB
    __shared__ float ws[32 * 64];   // [k][col] linear, 8 KB

    int tid = threadIdx.x;
    int cg  = tid & 7;    // column group: cols [cg*8, cg*8+8)
    int rg  = tid >> 3;   // row group:    rows [rg*8, rg*8+8)
    int r0 = rg * 8, c0 = cg * 8;
    int row_base = blockIdx.x * 128;

    unsigned long long acc[8][4];
#pragma unroll
    for (int r = 0; r < 8; r++)
#pragma unroll
        for (int j = 0; j < 4; j++) acc[r][j] = 0ULL;

    int myrow = row_base + tid;
    bool rowok = (myrow < N_NODES);
    const float4* xrow = (const float4*)(x + (size_t)myrow * D_IN);

    for (int kt = 0; kt < D_IN; kt += 32) {
        if (rowok) {
#pragma unroll
            for (int j = 0; j < 8; j++) {
                float4 v = xrow[(kt >> 2) + j];
                int kk = j * 4;
                xs[kk + 0][tid] = v.x;
                xs[kk + 1][tid] = v.y;
                xs[kk + 2][tid] = v.z;
                xs[kk + 3][tid] = v.w;
            }
        }
        {
            // W K-tile rows kt..kt+31 are a contiguous 2048-float region.
            const float4* wsrc = (const float4*)(w + kt * 64);
            float4*       wdst = (float4*)ws;
#pragma unroll
            for (int j = 0; j < 4; j++) wdst[tid + j * 128] = wsrc[tid + j * 128];
        }
        __syncthreads();

#pragma unroll
        for (int k = 0; k < 32; k++) {
            float4 a03 = *(const float4*)&xs[k][r0];
            float4 a47 = *(const float4*)&xs[k][r0 + 4];
            unsigned long long aa[8];
            PACKDUP(aa[0], a03.x); PACKDUP(aa[1], a03.y);
            PACKDUP(aa[2], a03.z); PACKDUP(aa[3], a03.w);
            PACKDUP(aa[4], a47.x); PACKDUP(aa[5], a47.y);
            PACKDUP(aa[6], a47.z); PACKDUP(aa[7], a47.w);

            const unsigned long long* bp =
                (const unsigned long long*)(ws + k * 64 + c0);
            unsigned long long b0 = bp[0], b1 = bp[1], b2 = bp[2], b3 = bp[3];
#pragma unroll
            for (int r = 0; r < 8; r++) {
                FMA2(acc[r][0], aa[r], b0);
                FMA2(acc[r][1], aa[r], b1);
                FMA2(acc[r][2], aa[r], b2);
                FMA2(acc[r][3], aa[r], b3);
            }
        }
        __syncthreads();
    }

#pragma unroll
    for (int r = 0; r < 8; r++) {
        int row = row_base + r0 + r;
        if (row < N_NODES) {
            unsigned long long* o =
                (unsigned long long*)(g_xw + (size_t)row * D_OUT + c0);
            o[0] = acc[r][0]; o[1] = acc[r][1];
            o[2] = acc[r][2]; o[3] = acc[r][3];
        }
    }
}

// ---------------- aggregate: one warp per node, regs accumulate, relu -------
// All offsets fit in 32 bits (xw is 25.6 MB): unsigned indexing avoids
// 64-bit IMAD chains in the hot loop.
__global__ __launch_bounds__(512) void k_agg(float* __restrict__ out) {
    int warp = (blockIdx.x * blockDim.x + threadIdx.x) >> 5;
    unsigned lane = threadIdx.x & 31;
    if (warp >= N_NODES) return;

    int beg = g_rowstart[warp];
    int end = g_rowstart[warp + 1];
    const float2* __restrict__ xw2 = (const float2*)g_xw;

    float2 acc = make_float2(0.f, 0.f);
    int e = beg;
    // unroll x4: 4 independent edge-rec -> row-gather chains in flight
    for (; e + 4 <= end; e += 4) {
        int2 r0 = g_sedge[e],     r1 = g_sedge[e + 1];
        int2 r2 = g_sedge[e + 2], r3 = g_sedge[e + 3];
        float2 v0 = xw2[(unsigned)r0.x * 32u + lane];
        float2 v1 = xw2[(unsigned)r1.x * 32u + lane];
        float2 v2 = xw2[(unsigned)r2.x * 32u + lane];
        float2 v3 = xw2[(unsigned)r3.x * 32u + lane];
        float w0 = __int_as_float(r0.y), w1 = __int_as_float(r1.y);
        float w2 = __int_as_float(r2.y), w3 = __int_as_float(r3.y);
        acc.x += w0 * v0.x; acc.y += w0 * v0.y;
        acc.x += w1 * v1.x; acc.y += w1 * v1.y;
        acc.x += w2 * v2.x; acc.y += w2 * v2.y;
        acc.x += w3 * v3.x; acc.y += w3 * v3.y;
    }
    for (; e < end; e++) {
        int2 r = g_sedge[e];
        float wv = __int_as_float(r.y);
        float2 v = xw2[(unsigned)r.x * 32u + lane];
        acc.x += wv * v.x; acc.y += wv * v.y;
    }
    acc.x = fmaxf(acc.x, 0.f);
    acc.y = fmaxf(acc.y, 0.f);
    ((float2*)out)[(unsigned)warp * 32u + lane] = acc;
}

// ---------------- launch -----------------------------------------------------
// Identify inputs by element count where unique (x: 12.8M, weight: 8192);
// the three 1.6M-element buffers keep dict order: edge_weight, src, dst.
extern "C" void kernel_launch(void* const* d_in, const int* in_sizes, int n_in,
                              void* d_out, int out_size) {
    const float* x    = (const float*)d_in[0];
    const float* ew   = (const float*)d_in[1];
    const float* w    = (const float*)d_in[2];
    const void*  esrc = (const void*)d_in[3];
    const void*  edst = (const void*)d_in[4];

    int em[3], nem = 0;   // positions of the 1.6M-element buffers, in order
    for (int i = 0; i < n_in && i < 8; i++) {
        long long sz = in_sizes[i];
        if (sz == (long long)N_NODES * D_IN)      x = (const float*)d_in[i];
        else if (sz == (long long)D_IN * D_OUT)   w = (const float*)d_in[i];
        else if (sz == (long long)N_EDGES && nem < 3) em[nem++] = i;
    }
    if (nem == 3) {
        ew   = (const float*)d_in[em[0]];
        esrc = d_in[em[1]];
        edst = d_in[em[2]];
    }
    float* out = (float*)d_out;

    k_detect<<<1, 64>>>((const unsigned long long*)esrc);
    k_zero<<<(N_NODES + 255) / 256, 256>>>();
    k_hist<<<(N_EDGES / 2 + 255) / 256, 256>>>(esrc);
    k_scan_a<<<NBCH, 256>>>();
    k_scan_b<<<1, 1>>>();
    k_scan_c<<<NBCH, 256>>>();
    k_scatter<<<(N_EDGES / 2 + 255) / 256, 256>>>(esrc, edst, ew);
    k_gemm<<<(N_NODES + 127) / 128, 128>>>(x, w);
    k_agg<<<(N_NODES * 32 + 511) / 512, 512>>>(out);
}